// round 13
// baseline (speedup 1.0000x reference)
#include <cuda_runtime.h>
#include <cuda_fp16.h>
#include <math.h>

// ---------------------------------------------------------------------------
// Pooler_8340826489238: multi-level RoIAlign (FPN pooler).
//   (1) ONE fused NCHW fp32 -> NHWC fp16 transpose kernel for all 4 levels
//   (2) pooling kernel: block=(roi, ch-half); per-bin tap descriptors in smem;
//       fp16 HFMA2 tap accumulation per sample, fp32 cross-sample combine.
// ---------------------------------------------------------------------------

#define NROI   1024
#define NCH    256
#define PH     7
#define PW     7
#define BINS   (PH * PW)         // 49

typedef unsigned long long ull;

// NHWC fp16 scratch, uint4 for 16B alignment.
__device__ uint4 g_t0[(2 * 200 * 200 * 256) / 8];  // 40.96 MB
__device__ uint4 g_t1[(2 * 100 * 100 * 256) / 8];  // 10.24 MB
__device__ uint4 g_t2[(2 * 50 * 50 * 256) / 8];    //  2.56 MB
__device__ uint4 g_t3[(2 * 25 * 25 * 256) / 8];    //  0.64 MB

// ----------------- fused NCHW fp32 -> NHWC fp16 transpose -------------------
#define TB0 10000
#define TB1 (TB0 + 2504)
#define TB2 (TB1 + 632)
#define TB3 (TB2 + 160)          // total grid

__global__ void __launch_bounds__(256)
transpose_all_kernel(const float* __restrict__ x0, const float* __restrict__ x1,
                     const float* __restrict__ x2, const float* __restrict__ x3) {
    __shared__ float tile[64][33];

    int bid = blockIdx.x;
    const float* in;
    __half2* outp;
    int HW, ntx, lb;
    if (bid < TB0)      { lb = bid;       in = x0; outp = (__half2*)g_t0; HW = 40000; ntx = 1250; }
    else if (bid < TB1) { lb = bid - TB0; in = x1; outp = (__half2*)g_t1; HW = 10000; ntx = 313; }
    else if (bid < TB2) { lb = bid - TB1; in = x2; outp = (__half2*)g_t2; HW = 2500;  ntx = 79; }
    else                { lb = bid - TB2; in = x3; outp = (__half2*)g_t3; HW = 625;   ntx = 20; }

    int tile_x = lb % ntx;
    int rest   = lb / ntx;
    int cgrp   = rest & 3;
    int b      = rest >> 2;

    int c0  = cgrp * 64;
    int hw0 = tile_x * 32;
    int tx  = threadIdx.x;
    int ty  = threadIdx.y;

    const float* in_b = in + (size_t)b * NCH * HW;

#pragma unroll
    for (int i = 0; i < 8; i++) {
        int c  = c0 + ty + i * 8;
        int hw = hw0 + tx;
        if (hw < HW)
            tile[ty + i * 8][tx] = in_b[(size_t)c * HW + hw];
    }
    __syncthreads();

    __half2* out_b = outp + (size_t)b * HW * (NCH / 2);
#pragma unroll
    for (int i = 0; i < 4; i++) {
        int row = ty + i * 8;
        int hw  = hw0 + row;
        if (hw < HW) {
            float lo = tile[2 * tx][row];
            float hi = tile[2 * tx + 1][row];
            out_b[(size_t)hw * (NCH / 2) + (c0 >> 1) + tx] =
                __floats2half2_rn(lo, hi);
        }
    }
}

// ---- one axis of the torchvision bilinear clamp (matches reference exactly)
struct Axis { int lo; int hi; float lf; float hf; };

__device__ __forceinline__ Axis axis_interp(float v, int H) {
    Axis a;
    bool empty = (v < -1.0f) || (v > (float)H);
    v = fmaxf(v, 0.0f);
    float fl = floorf(v);
    int l, h;
    if (fl >= (float)(H - 1)) {
        v = (float)(H - 1);
        l = H - 1; h = H - 1;
    } else {
        l = (int)fl; h = l + 1;
    }
    a.lf = v - (float)l;
    a.hf = 1.0f - a.lf;
    if (empty) { a.lf = 0.0f; a.hf = 0.0f; }
    a.lo = l; a.hi = h;
    return a;
}

// ---------------- packed f32x2 helpers (Blackwell, PTX-only) ----------------
__device__ __forceinline__ ull pack2(float lo, float hi) {
    ull r; asm("mov.b64 %0, {%1, %2};" : "=l"(r) : "f"(lo), "f"(hi)); return r;
}
__device__ __forceinline__ float2 unpack2(ull v) {
    float2 r; asm("mov.b64 {%0, %1}, %2;" : "=f"(r.x), "=f"(r.y) : "l"(v)); return r;
}
__device__ __forceinline__ void fma2(ull& acc, ull v, ull w) {
    asm("fma.rn.f32x2 %0, %1, %2, %0;" : "+l"(acc) : "l"(v), "l"(w));
}
__device__ __forceinline__ __half2 u2h(unsigned int u) {
    __half2 h; *(unsigned int*)&h = u; return h;
}

// ------------------------------- pooling ------------------------------------
// Block = (roi, channel-half). 256 threads: warp lanes cover 128 channels
// (4 ch/lane via LDG.64); 8 warps stride the 49 bins.
// Per (bin,sample) descriptor: 4 tap offsets (int4) + 4 fp16 weights (uint4
// of half2 pairs). Taps accumulated in fp16 (HMUL2/HFMA2); each sample's
// result converted to fp32 and combined with the 0.25 sample weight (FFMA2).
#define OPITCH 133   // 133 mod 32 = 5 -> conflict-free strided readback

__global__ void __launch_bounds__(256)
pool_f16_kernel(const float* __restrict__ boxes, float* __restrict__ out) {
    __shared__ int4  offs[BINS * 4];          // per (bin,sample): 4 tap offsets
    __shared__ uint4 wh  [BINS * 4];          // per (bin,sample): 4 half2 weights
    __shared__ float sbins[BINS * OPITCH];    // [bin][128ch]

    int r    = blockIdx.x;
    int half = blockIdx.y;
    int tid  = threadIdx.x;
    int lane = tid & 31;
    int warp = tid >> 5;

    // ---- inline per-ROI meta (every thread, registers only) ----
    float bx1 = __ldg(boxes + r * 4 + 0);
    float by1 = __ldg(boxes + r * 4 + 1);
    float bx2 = __ldg(boxes + r * 4 + 2);
    float by2 = __ldg(boxes + r * 4 + 3);
    float area = (bx2 - bx1) * (by2 - by1);
    float s    = sqrtf(area);
    float lvlf = floorf(4.0f + log2f(s / 224.0f + 1e-6f));
    lvlf       = fminf(fmaxf(lvlf, 2.0f), 5.0f);
    int level  = (int)lvlf - 2;                       // 0..3

    float scale = 0.25f / (float)(1 << level);
    float x1s = bx1 * scale, y1s = by1 * scale;
    float roi_w = fmaxf(bx2 * scale - x1s, 1.0f);
    float roi_h = fmaxf(by2 * scale - y1s, 1.0f);
    float bin_w = roi_w * (1.0f / (float)PW);
    float bin_h = roi_h * (1.0f / (float)PH);

    const uint2* lvl;
    int H;
    if (level == 0)      { lvl = (const uint2*)g_t0; H = 200; }
    else if (level == 1) { lvl = (const uint2*)g_t1; H = 100; }
    else if (level == 2) { lvl = (const uint2*)g_t2; H = 50;  }
    else                 { lvl = (const uint2*)g_t3; H = 25;  }
    int W  = H;
    int HW = H * W;
    int batch = r >> 9;

    // ---- precompute 196 descriptors: tid < 196 -> (bin, sample) ----
    if (tid < BINS * 4) {
        int bin = tid >> 2;
        int smp = tid & 3;
        int sy  = smp >> 1;
        int sx  = smp & 1;
        int ph  = bin / PW;
        int pw  = bin - ph * PW;

        float vy = y1s + (float)ph * bin_h + ((float)sy + 0.5f) * 0.5f * bin_h;
        float vx = x1s + (float)pw * bin_w + ((float)sx + 0.5f) * 0.5f * bin_w;
        Axis ay = axis_interp(vy, H);
        Axis ax = axis_interp(vx, W);

        offs[tid] = make_int4((ay.lo * W + ax.lo) * 64,
                              (ay.lo * W + ax.hi) * 64,
                              (ay.hi * W + ax.lo) * 64,
                              (ay.hi * W + ax.hi) * 64);
        float wll = ay.hf * ax.hf;
        float wlh = ay.hf * ax.lf;
        float whl = ay.lf * ax.hf;
        float whh = ay.lf * ax.lf;
        __half2 h0 = __floats2half2_rn(wll, wll);
        __half2 h1 = __floats2half2_rn(wlh, wlh);
        __half2 h2 = __floats2half2_rn(whl, whl);
        __half2 h3 = __floats2half2_rn(whh, whh);
        wh[tid] = make_uint4(*(unsigned int*)&h0, *(unsigned int*)&h1,
                             *(unsigned int*)&h2, *(unsigned int*)&h3);
    }
    __syncthreads();

    const ull QUARTER = pack2(0.25f, 0.25f);

    // uint2 = 4 halves = 4 channels; 64 uint2 per pixel (256 ch).
    const uint2* base = lvl + (size_t)batch * HW * 64 + half * 32 + lane;

    for (int b = warp; b < BINS; b += 8) {
        int d = b * 4;
        ull acc0 = 0ULL, acc1 = 0ULL;     // (ch0,ch1), (ch2,ch3)
#pragma unroll
        for (int smp = 0; smp < 4; smp++) {
            int4  o = offs[d + smp];                      // uniform LDS.128
            uint4 w = wh[d + smp];                        // uniform LDS.128
            uint2 v0 = __ldg(base + o.x);
            uint2 v1 = __ldg(base + o.y);
            uint2 v2 = __ldg(base + o.z);
            uint2 v3 = __ldg(base + o.w);
            __half2 w0 = u2h(w.x), w1 = u2h(w.y), w2 = u2h(w.z), w3 = u2h(w.w);
            // fp16 accumulate the 4 taps of this sample
            __half2 alo = __hmul2(w0, u2h(v0.x));
            __half2 ahi = __hmul2(w0, u2h(v0.y));
            alo = __hfma2(w1, u2h(v1.x), alo);
            ahi = __hfma2(w1, u2h(v1.y), ahi);
            alo = __hfma2(w2, u2h(v2.x), alo);
            ahi = __hfma2(w2, u2h(v2.y), ahi);
            alo = __hfma2(w3, u2h(v3.x), alo);
            ahi = __hfma2(w3, u2h(v3.y), ahi);
            // one conversion per sample, fp32 combine with 0.25 weight
            float2 flo = __half22float2(alo);
            float2 fhi = __half22float2(ahi);
            fma2(acc0, pack2(flo.x, flo.y), QUARTER);
            fma2(acc1, pack2(fhi.x, fhi.y), QUARTER);
        }
        float2 a01 = unpack2(acc0);
        float2 a23 = unpack2(acc1);
        float* sp = &sbins[b * OPITCH + lane * 4];
        sp[0] = a01.x;
        sp[1] = a01.y;
        sp[2] = a23.x;
        sp[3] = a23.y;
    }
    __syncthreads();

    // coalesced c-major writeout, div-free indexing: i = cl*49 + b
    float* ob = out + (size_t)r * (NCH * BINS) + half * (128 * BINS);
    int b  = tid % BINS;
    int cl = tid / BINS;
    for (int i = tid; i < 128 * BINS; i += 256) {
        ob[i] = sbins[b * OPITCH + cl];
        b += 11; cl += 5;                 // 256 = 5*49 + 11
        if (b >= BINS) { b -= BINS; cl++; }
    }
}

// --------------------------------- launch -----------------------------------
extern "C" void kernel_launch(void* const* d_in, const int* in_sizes, int n_in,
                              void* d_out, int out_size) {
    const float* x0    = (const float*)d_in[0];
    const float* x1    = (const float*)d_in[1];
    const float* x2    = (const float*)d_in[2];
    const float* x3    = (const float*)d_in[3];
    const float* boxes = (const float*)d_in[4];
    float* out = (float*)d_out;

    dim3 blk(32, 8);
    transpose_all_kernel<<<TB3, blk>>>(x0, x1, x2, x3);

    pool_f16_kernel<<<dim3(NROI, 2), 256>>>(boxes, out);
}